// round 2
// baseline (speedup 1.0000x reference)
#include <cuda_runtime.h>

#define DD   768
#define BB   8
#define SS   2048
#define MTOT (BB * SS)

// Scratch (device globals — no allocations allowed in kernel_launch)
__device__ float g_xn[(size_t)MTOT * DD];          // 48 MB  LayerNorm output
__device__ float g_q [(size_t)MTOT * DD];          // 48 MB  Q
__device__ float g_k [(size_t)MTOT * DD];          // 48 MB  K
__device__ float g_p [(size_t)BB * SS * SS];       // 134 MB scores / attn probs

// ---------------------------------------------------------------------------
// Block reductions
// ---------------------------------------------------------------------------
__device__ __forceinline__ float blockReduceSum(float v) {
    __shared__ float sh[32];
    int lane = threadIdx.x & 31, wid = threadIdx.x >> 5;
    #pragma unroll
    for (int o = 16; o; o >>= 1) v += __shfl_down_sync(0xffffffffu, v, o);
    if (lane == 0) sh[wid] = v;
    __syncthreads();
    int nw = blockDim.x >> 5;
    float r = (threadIdx.x < (unsigned)nw) ? sh[threadIdx.x] : 0.f;
    if (wid == 0) {
        #pragma unroll
        for (int o = 16; o; o >>= 1) r += __shfl_down_sync(0xffffffffu, r, o);
        if (lane == 0) sh[0] = r;
    }
    __syncthreads();
    float out = sh[0];
    __syncthreads();
    return out;
}

__device__ __forceinline__ float blockReduceMax(float v) {
    __shared__ float sh[32];
    int lane = threadIdx.x & 31, wid = threadIdx.x >> 5;
    #pragma unroll
    for (int o = 16; o; o >>= 1) v = fmaxf(v, __shfl_down_sync(0xffffffffu, v, o));
    if (lane == 0) sh[wid] = v;
    __syncthreads();
    int nw = blockDim.x >> 5;
    float r = (threadIdx.x < (unsigned)nw) ? sh[threadIdx.x] : -3.4e38f;
    if (wid == 0) {
        #pragma unroll
        for (int o = 16; o; o >>= 1) r = fmaxf(r, __shfl_down_sync(0xffffffffu, r, o));
        if (lane == 0) sh[0] = r;
    }
    __syncthreads();
    float out = sh[0];
    __syncthreads();
    return out;
}

// ---------------------------------------------------------------------------
// LayerNorm: one block per row (256 threads, 3 elems each)
// ---------------------------------------------------------------------------
__global__ __launch_bounds__(256) void ln_kernel(const float* __restrict__ x,
                                                 const float* __restrict__ g,
                                                 const float* __restrict__ b) {
    int row = blockIdx.x;
    const float* xr = x + (size_t)row * DD;
    int t = threadIdx.x;
    float v[3];
    #pragma unroll
    for (int i = 0; i < 3; i++) v[i] = xr[t + i * 256];
    float mean = blockReduceSum(v[0] + v[1] + v[2]) * (1.0f / DD);
    float q = 0.f;
    #pragma unroll
    for (int i = 0; i < 3; i++) { float d = v[i] - mean; q += d * d; }
    float var = blockReduceSum(q) * (1.0f / DD);
    float inv = rsqrtf(var + 1e-5f);
    float* o = g_xn + (size_t)row * DD;
    #pragma unroll
    for (int i = 0; i < 3; i++) {
        int c = t + i * 256;
        o[c] = (v[i] - mean) * inv * g[c] + b[c];
    }
}

// ---------------------------------------------------------------------------
// Tiled fp32 GEMM body: 64x64 tile, BK=16, 256 threads, 4x4 register block.
// TRANSB=true : C[m,n] = alpha * sum_k A[m,k]*B[n,k]   (B is [N,K] row-major)
// TRANSB=false: C[m,n] = alpha * sum_k A[m,k]*B[k,n]   (B is [K,N] row-major)
// All dims assumed multiples of 64 (M,N) and 16 (K) — true for this problem.
// ---------------------------------------------------------------------------
template <bool TRANSB, bool BIAS, bool RESID>
__device__ __forceinline__ void gemm_body(const float* __restrict__ A,
                                          const float* __restrict__ Bm,
                                          float* __restrict__ C,
                                          int N, int K, float alpha,
                                          const float* __restrict__ bias,
                                          const float* __restrict__ resid) {
    __shared__ float As[16][68];
    __shared__ float Bs[16][68];
    const int tid = threadIdx.x;
    const int m0 = blockIdx.y * 64;
    const int n0 = blockIdx.x * 64;
    const int tx = tid & 15;   // n sub-block
    const int ty = tid >> 4;   // m sub-block

    float acc[4][4];
    #pragma unroll
    for (int i = 0; i < 4; i++)
        #pragma unroll
        for (int j = 0; j < 4; j++) acc[i][j] = 0.f;

    for (int k0 = 0; k0 < K; k0 += 16) {
        // Load A tile: 64 rows x 16 k
        {
            int row = tid >> 2, kq = (tid & 3) * 4;
            float4 v = *(const float4*)(A + (size_t)(m0 + row) * K + k0 + kq);
            As[kq + 0][row] = v.x; As[kq + 1][row] = v.y;
            As[kq + 2][row] = v.z; As[kq + 3][row] = v.w;
        }
        if (TRANSB) {
            int row = tid >> 2, kq = (tid & 3) * 4;
            float4 v = *(const float4*)(Bm + (size_t)(n0 + row) * K + k0 + kq);
            Bs[kq + 0][row] = v.x; Bs[kq + 1][row] = v.y;
            Bs[kq + 2][row] = v.z; Bs[kq + 3][row] = v.w;
        } else {
            int kk = tid >> 4, nq = (tid & 15) * 4;
            float4 v = *(const float4*)(Bm + (size_t)(k0 + kk) * N + n0 + nq);
            *(float4*)&Bs[kk][nq] = v;
        }
        __syncthreads();

        #pragma unroll
        for (int kk = 0; kk < 16; kk++) {
            float a[4], bv[4];
            #pragma unroll
            for (int i = 0; i < 4; i++) a[i]  = As[kk][ty * 4 + i];
            #pragma unroll
            for (int j = 0; j < 4; j++) bv[j] = Bs[kk][tx * 4 + j];
            #pragma unroll
            for (int i = 0; i < 4; i++)
                #pragma unroll
                for (int j = 0; j < 4; j++)
                    acc[i][j] = fmaf(a[i], bv[j], acc[i][j]);
        }
        __syncthreads();
    }

    #pragma unroll
    for (int i = 0; i < 4; i++) {
        int r = m0 + ty * 4 + i;
        #pragma unroll
        for (int j = 0; j < 4; j++) {
            int c = n0 + tx * 4 + j;
            float v = acc[i][j] * alpha;
            if (BIAS)  v += bias[c];
            if (RESID) v += resid[(size_t)r * N + c];
            C[(size_t)r * N + c] = v;
        }
    }
}

// Q/K projection: C = xn @ W^T + b   (M=16384, N=768, K=768)
__global__ __launch_bounds__(256) void proj_kernel(const float* __restrict__ W,
                                                   const float* __restrict__ bias,
                                                   int which) {
    float* C = which ? g_k : g_q;
    gemm_body<true, true, false>(g_xn, W, C, DD, DD, 1.0f, bias, nullptr);
}

// scores: P[b] = (Q[b] @ K[b]^T) / sqrt(D)   (M=N=2048, K=768), blockIdx.z = batch
__global__ __launch_bounds__(256) void scores_kernel() {
    size_t bo = (size_t)blockIdx.z * SS * DD;
    gemm_body<true, false, false>(g_q + bo, g_k + bo,
                                  g_p + (size_t)blockIdx.z * SS * SS,
                                  SS, DD, 0.036084391824351615f, nullptr, nullptr);
}

// softmax over last dim (2048), one block per row
__global__ __launch_bounds__(256) void softmax_kernel() {
    float* row = g_p + (size_t)blockIdx.x * SS;
    int t = threadIdx.x;
    float v[8];
    #pragma unroll
    for (int i = 0; i < 8; i++) v[i] = row[t + i * 256];
    float m = v[0];
    #pragma unroll
    for (int i = 1; i < 8; i++) m = fmaxf(m, v[i]);
    m = blockReduceMax(m);
    float s = 0.f;
    #pragma unroll
    for (int i = 0; i < 8; i++) { v[i] = __expf(v[i] - m); s += v[i]; }
    s = blockReduceSum(s);
    float inv = 1.0f / s;
    #pragma unroll
    for (int i = 0; i < 8; i++) row[t + i * 256] = v[i] * inv;
}

// out[b] = P[b] @ x[b] + x[b]   (M=2048, N=768, K=2048), blockIdx.z = batch
__global__ __launch_bounds__(256) void av_kernel(const float* __restrict__ x,
                                                 float* __restrict__ out) {
    size_t xo = (size_t)blockIdx.z * SS * DD;
    gemm_body<false, false, true>(g_p + (size_t)blockIdx.z * SS * SS,
                                  x + xo, out + xo, DD, SS, 1.0f,
                                  nullptr, x + xo);
}

// ---------------------------------------------------------------------------
extern "C" void kernel_launch(void* const* d_in, const int* in_sizes, int n_in,
                              void* d_out, int out_size) {
    const float* x    = (const float*)d_in[0];
    const float* ln_g = (const float*)d_in[1];
    const float* ln_b = (const float*)d_in[2];
    const float* Wq   = (const float*)d_in[3];
    const float* bq   = (const float*)d_in[4];
    const float* Wk   = (const float*)d_in[5];
    const float* bk   = (const float*)d_in[6];
    float* out = (float*)d_out;

    ln_kernel<<<MTOT, 256>>>(x, ln_g, ln_b);

    dim3 gp(DD / 64, MTOT / 64);
    proj_kernel<<<gp, 256>>>(Wq, bq, 0);
    proj_kernel<<<gp, 256>>>(Wk, bk, 1);

    scores_kernel<<<dim3(SS / 64, SS / 64, BB), 256>>>();
    softmax_kernel<<<BB * SS, 256>>>();
    av_kernel<<<dim3(DD / 64, SS / 64, BB), 256>>>(x, out);
}

// round 4
// speedup vs baseline: 5.4597x; 5.4597x over previous
#include <cuda_runtime.h>
#include <cuda_bf16.h>

#define DD   768
#define BB   8
#define SS   2048
#define MTOT (BB * SS)
#define BK   32

typedef unsigned int u32;

// ---------------------------------------------------------------------------
// Device scratch (no allocations allowed)
// ---------------------------------------------------------------------------
__device__ __nv_bfloat16 g_xn[(size_t)MTOT * DD];      // LN output (bf16)
__device__ __nv_bfloat16 g_wq[(size_t)DD * DD];        // Wq bf16
__device__ __nv_bfloat16 g_wk[(size_t)DD * DD];        // Wk bf16
__device__ __nv_bfloat16 g_q [(size_t)MTOT * DD];      // Q bf16
__device__ __nv_bfloat16 g_k [(size_t)MTOT * DD];      // K bf16
__device__ float         g_p [(size_t)BB * SS * SS];   // scores fp32
__device__ __nv_bfloat16 g_pb[(size_t)BB * SS * SS];   // probs bf16
__device__ __nv_bfloat16 g_xt[(size_t)BB * DD * SS];   // x^T bf16 [b][d][s]

// ---------------------------------------------------------------------------
__device__ __forceinline__ u32 smem_u32(const void* p) {
    u32 a;
    asm("{ .reg .u64 t; cvta.to.shared.u64 t, %1; cvt.u32.u64 %0, t; }" : "=r"(a) : "l"(p));
    return a;
}
#define CP_ASYNC16(sa, ga) \
    asm volatile("cp.async.cg.shared.global [%0], [%1], 16;" :: "r"(sa), "l"(ga) : "memory")
#define CP_COMMIT()  asm volatile("cp.async.commit_group;" ::: "memory")
#define CP_WAIT(n)   asm volatile("cp.async.wait_group %0;" :: "n"(n) : "memory")

__device__ __forceinline__ void mma16816(float* c, const u32* a, const u32* b) {
    asm volatile(
        "mma.sync.aligned.m16n8k16.row.col.f32.bf16.bf16.f32 "
        "{%0,%1,%2,%3}, {%4,%5,%6,%7}, {%8,%9}, {%0,%1,%2,%3};"
        : "+f"(c[0]), "+f"(c[1]), "+f"(c[2]), "+f"(c[3])
        : "r"(a[0]), "r"(a[1]), "r"(a[2]), "r"(a[3]), "r"(b[0]), "r"(b[1]));
}

// ---------------------------------------------------------------------------
// HMMA GEMM:  C[m,n] = sum_k A[m,k] * B[n,k]  (+bias)(+resid)
// A:[M,K] bf16 K-major, B:[N,K] bf16 K-major. Block 128x128, BK=32.
// 256 threads = 8 warps (4m x 2n), warp tile 32x64, m16n8k16 fragments.
// SMEM rows padded to 40 bf16 (80B) -> conflict-free b32 fragment LDS.
// ---------------------------------------------------------------------------
template <bool BIAS, bool RESID, bool OUTBF16>
__global__ __launch_bounds__(256) void mma_gemm(
    const __nv_bfloat16* __restrict__ A, const __nv_bfloat16* __restrict__ B,
    void* __restrict__ Cv,
    const float* __restrict__ bias, const float* __restrict__ resid,
    int N, int K, long aStride, long bStride, long cStride)
{
    __shared__ __align__(16) __nv_bfloat16 As[2][128][40];
    __shared__ __align__(16) __nv_bfloat16 Bs[2][128][40];

    const int tid = threadIdx.x;
    const int wid = tid >> 5, lane = tid & 31;
    const int wm = wid & 3, wn = wid >> 2;          // 4 x 2 warp grid
    const int g = lane >> 2, t = lane & 3;          // mma fragment coords
    const int m0 = blockIdx.y * 128, n0 = blockIdx.x * 128;
    const int z = blockIdx.z;

    A += (size_t)z * aStride + (size_t)m0 * K;
    B += (size_t)z * bStride + (size_t)n0 * K;

    const int NC = K / BK;
    // each thread loads 2 x 16B for A and 2 x 16B for B per stage
    const int r0 = tid >> 2, c0 = (tid & 3) * 8;          // segment 0
    const int r1 = (tid + 256) >> 2;                      // segment 1 (same c0)

    float acc[2][8][4];
    #pragma unroll
    for (int mt = 0; mt < 2; mt++)
        #pragma unroll
        for (int nt = 0; nt < 8; nt++)
            #pragma unroll
            for (int i = 0; i < 4; i++) acc[mt][nt][i] = 0.f;

    // prologue: stage 0
    {
        CP_ASYNC16(smem_u32(&As[0][r0][c0]), A + (size_t)r0 * K + c0);
        CP_ASYNC16(smem_u32(&As[0][r1][c0]), A + (size_t)r1 * K + c0);
        CP_ASYNC16(smem_u32(&Bs[0][r0][c0]), B + (size_t)r0 * K + c0);
        CP_ASYNC16(smem_u32(&Bs[0][r1][c0]), B + (size_t)r1 * K + c0);
        CP_COMMIT();
    }

    for (int c = 0; c < NC; ++c) {
        const int buf = c & 1;
        if (c + 1 < NC) {
            const int nb = buf ^ 1;
            const __nv_bfloat16* Ak = A + (size_t)(c + 1) * BK;
            const __nv_bfloat16* Bk = B + (size_t)(c + 1) * BK;
            CP_ASYNC16(smem_u32(&As[nb][r0][c0]), Ak + (size_t)r0 * K + c0);
            CP_ASYNC16(smem_u32(&As[nb][r1][c0]), Ak + (size_t)r1 * K + c0);
            CP_ASYNC16(smem_u32(&Bs[nb][r0][c0]), Bk + (size_t)r0 * K + c0);
            CP_ASYNC16(smem_u32(&Bs[nb][r1][c0]), Bk + (size_t)r1 * K + c0);
            CP_COMMIT();
            CP_WAIT(1);
        } else {
            CP_WAIT(0);
        }
        __syncthreads();

        #pragma unroll
        for (int kk = 0; kk < 2; kk++) {
            const int kb = kk * 16 + 2 * t;
            u32 bfr[8][2];
            #pragma unroll
            for (int nt = 0; nt < 8; nt++) {
                const __nv_bfloat16* p = &Bs[buf][wn * 64 + nt * 8 + g][kb];
                bfr[nt][0] = *(const u32*)p;
                bfr[nt][1] = *(const u32*)(p + 8);
            }
            #pragma unroll
            for (int mt = 0; mt < 2; mt++) {
                u32 afr[4];
                const __nv_bfloat16* p0 = &As[buf][wm * 32 + mt * 16 + g][kb];
                const __nv_bfloat16* p1 = &As[buf][wm * 32 + mt * 16 + 8 + g][kb];
                afr[0] = *(const u32*)p0;
                afr[1] = *(const u32*)p1;
                afr[2] = *(const u32*)(p0 + 8);
                afr[3] = *(const u32*)(p1 + 8);
                #pragma unroll
                for (int nt = 0; nt < 8; nt++)
                    mma16816(acc[mt][nt], afr, bfr[nt]);
            }
        }
        __syncthreads();
    }

    // Epilogue
    #pragma unroll
    for (int mt = 0; mt < 2; mt++) {
        #pragma unroll
        for (int nt = 0; nt < 8; nt++) {
            const int row = m0 + wm * 32 + mt * 16 + g;
            const int col = n0 + wn * 64 + nt * 8 + 2 * t;
            float v0 = acc[mt][nt][0], v1 = acc[mt][nt][1];
            float v2 = acc[mt][nt][2], v3 = acc[mt][nt][3];
            if (BIAS) {
                float b0 = bias[col], b1 = bias[col + 1];
                v0 += b0; v1 += b1; v2 += b0; v3 += b1;
            }
            if (OUTBF16) {
                __nv_bfloat16* Cb = (__nv_bfloat16*)Cv + (size_t)z * cStride;
                *(__nv_bfloat162*)(Cb + (size_t)row * N + col) = __floats2bfloat162_rn(v0, v1);
                *(__nv_bfloat162*)(Cb + (size_t)(row + 8) * N + col) = __floats2bfloat162_rn(v2, v3);
            } else {
                float* Cf = (float*)Cv + (size_t)z * cStride;
                if (RESID) {
                    const float* R = resid + (size_t)z * cStride;
                    float2 ra = *(const float2*)(R + (size_t)row * N + col);
                    float2 rb = *(const float2*)(R + (size_t)(row + 8) * N + col);
                    v0 += ra.x; v1 += ra.y; v2 += rb.x; v3 += rb.y;
                }
                *(float2*)(Cf + (size_t)row * N + col) = make_float2(v0, v1);
                *(float2*)(Cf + (size_t)(row + 8) * N + col) = make_float2(v2, v3);
            }
        }
    }
}

// ---------------------------------------------------------------------------
// Reductions + elementwise kernels
// ---------------------------------------------------------------------------
__device__ __forceinline__ float blockReduceSum(float v) {
    __shared__ float sh[32];
    int lane = threadIdx.x & 31, wid = threadIdx.x >> 5;
    #pragma unroll
    for (int o = 16; o; o >>= 1) v += __shfl_down_sync(0xffffffffu, v, o);
    if (lane == 0) sh[wid] = v;
    __syncthreads();
    float r = (threadIdx.x < (blockDim.x >> 5)) ? sh[threadIdx.x] : 0.f;
    if (wid == 0) {
        #pragma unroll
        for (int o = 16; o; o >>= 1) r += __shfl_down_sync(0xffffffffu, r, o);
        if (lane == 0) sh[0] = r;
    }
    __syncthreads();
    float out = sh[0];
    __syncthreads();
    return out;
}
__device__ __forceinline__ float blockReduceMax(float v) {
    __shared__ float sh[32];
    int lane = threadIdx.x & 31, wid = threadIdx.x >> 5;
    #pragma unroll
    for (int o = 16; o; o >>= 1) v = fmaxf(v, __shfl_down_sync(0xffffffffu, v, o));
    if (lane == 0) sh[wid] = v;
    __syncthreads();
    float r = (threadIdx.x < (blockDim.x >> 5)) ? sh[threadIdx.x] : -3.4e38f;
    if (wid == 0) {
        #pragma unroll
        for (int o = 16; o; o >>= 1) r = fmaxf(r, __shfl_down_sync(0xffffffffu, r, o));
        if (lane == 0) sh[0] = r;
    }
    __syncthreads();
    float out = sh[0];
    __syncthreads();
    return out;
}

__global__ __launch_bounds__(256) void ln_kernel(const float* __restrict__ x,
                                                 const float* __restrict__ g,
                                                 const float* __restrict__ b) {
    int row = blockIdx.x, t = threadIdx.x;
    const float* xr = x + (size_t)row * DD;
    float v[3];
    #pragma unroll
    for (int i = 0; i < 3; i++) v[i] = xr[t + i * 256];
    float mean = blockReduceSum(v[0] + v[1] + v[2]) * (1.0f / DD);
    float q = 0.f;
    #pragma unroll
    for (int i = 0; i < 3; i++) { float d = v[i] - mean; q += d * d; }
    float inv = rsqrtf(blockReduceSum(q) * (1.0f / DD) + 1e-5f);
    __nv_bfloat16* o = g_xn + (size_t)row * DD;
    #pragma unroll
    for (int i = 0; i < 3; i++) {
        int c = t + i * 256;
        o[c] = __float2bfloat16_rn((v[i] - mean) * inv * g[c] + b[c]);
    }
}

__global__ __launch_bounds__(256) void convw_kernel(const float* __restrict__ Wq,
                                                    const float* __restrict__ Wk) {
    int i = blockIdx.x * 256 + threadIdx.x;
    if (i < DD * DD) {
        g_wq[i] = __float2bfloat16_rn(Wq[i]);
        g_wk[i] = __float2bfloat16_rn(Wk[i]);
    }
}

__global__ __launch_bounds__(256) void transpose_kernel(const float* __restrict__ x) {
    __shared__ float t[32][33];
    int b = blockIdx.z;
    int s0 = blockIdx.x * 32, d0 = blockIdx.y * 32;
    int tx = threadIdx.x & 31, ty = threadIdx.x >> 5;
    #pragma unroll
    for (int i = 0; i < 4; i++)
        t[ty + i * 8][tx] = x[(size_t)b * SS * DD + (size_t)(s0 + ty + i * 8) * DD + d0 + tx];
    __syncthreads();
    #pragma unroll
    for (int i = 0; i < 4; i++)
        g_xt[(size_t)b * DD * SS + (size_t)(d0 + ty + i * 8) * SS + s0 + tx] =
            __float2bfloat16_rn(t[tx][ty + i * 8]);
}

__global__ __launch_bounds__(256) void softmax_kernel() {
    const float alpha = 0.036084391824351615f;   // 1/sqrt(768)
    const float* row = g_p + (size_t)blockIdx.x * SS;
    __nv_bfloat16* orow = g_pb + (size_t)blockIdx.x * SS;
    int t = threadIdx.x;
    float v[8];
    #pragma unroll
    for (int i = 0; i < 8; i++) v[i] = row[t + i * 256] * alpha;
    float m = v[0];
    #pragma unroll
    for (int i = 1; i < 8; i++) m = fmaxf(m, v[i]);
    m = blockReduceMax(m);
    float s = 0.f;
    #pragma unroll
    for (int i = 0; i < 8; i++) { v[i] = __expf(v[i] - m); s += v[i]; }
    s = blockReduceSum(s);
    float inv = 1.0f / s;
    #pragma unroll
    for (int i = 0; i < 8; i++) orow[t + i * 256] = __float2bfloat16_rn(v[i] * inv);
}

// ---------------------------------------------------------------------------
extern "C" void kernel_launch(void* const* d_in, const int* in_sizes, int n_in,
                              void* d_out, int out_size) {
    const float* x    = (const float*)d_in[0];
    const float* ln_g = (const float*)d_in[1];
    const float* ln_b = (const float*)d_in[2];
    const float* Wq   = (const float*)d_in[3];
    const float* bq   = (const float*)d_in[4];
    const float* Wk   = (const float*)d_in[5];
    const float* bk   = (const float*)d_in[6];
    float* out = (float*)d_out;

    __nv_bfloat16 *p_xn, *p_wq, *p_wk, *p_q, *p_k, *p_pb, *p_xt;
    float* p_p;
    cudaGetSymbolAddress((void**)&p_xn, g_xn);
    cudaGetSymbolAddress((void**)&p_wq, g_wq);
    cudaGetSymbolAddress((void**)&p_wk, g_wk);
    cudaGetSymbolAddress((void**)&p_q,  g_q);
    cudaGetSymbolAddress((void**)&p_k,  g_k);
    cudaGetSymbolAddress((void**)&p_p,  g_p);
    cudaGetSymbolAddress((void**)&p_pb, g_pb);
    cudaGetSymbolAddress((void**)&p_xt, g_xt);

    ln_kernel<<<MTOT, 256>>>(x, ln_g, ln_b);
    convw_kernel<<<(DD * DD + 255) / 256, 256>>>(Wq, Wk);
    transpose_kernel<<<dim3(SS / 32, DD / 32, BB), 256>>>(x);

    // Q = xn @ Wq^T + bq ; K = xn @ Wk^T + bk   (M=16384, N=768, K=768)
    mma_gemm<true, false, true><<<dim3(DD / 128, MTOT / 128, 1), 256>>>(
        p_xn, p_wq, p_q, bq, nullptr, DD, DD, 0, 0, 0);
    mma_gemm<true, false, true><<<dim3(DD / 128, MTOT / 128, 1), 256>>>(
        p_xn, p_wk, p_k, bk, nullptr, DD, DD, 0, 0, 0);

    // scores = Q @ K^T (unscaled; softmax applies 1/sqrt(D))
    mma_gemm<false, false, false><<<dim3(SS / 128, SS / 128, BB), 256>>>(
        p_q, p_k, p_p, nullptr, nullptr, SS, DD,
        (long)SS * DD, (long)SS * DD, (long)SS * SS);

    softmax_kernel<<<BB * SS, 256>>>();

    // out = P @ x + x   (A = P bf16 [S,S], B = x^T bf16 [D,S])
    mma_gemm<false, true, false><<<dim3(DD / 128, SS / 128, BB), 256>>>(
        p_pb, p_xt, out, nullptr, x, DD, SS,
        (long)SS * SS, (long)DD * SS, (long)SS * DD);
}

// round 5
// speedup vs baseline: 6.6405x; 1.2163x over previous
#include <cuda_runtime.h>
#include <cuda_bf16.h>

#define DD   768
#define BB   8
#define SS   2048
#define MTOT (BB * SS)
#define BK   32
#define PITCH 40                        // bf16 per smem row (80B, conflict-free)
#define STAGE_BYTES (128 * PITCH * 2)   // 10240 per operand tile
#define NSTAGE 3

typedef unsigned int u32;

// ---------------------------------------------------------------------------
// Device scratch (no allocations allowed)
// ---------------------------------------------------------------------------
__device__ __nv_bfloat16 g_xn[(size_t)MTOT * DD];      // LN output (bf16)
__device__ __nv_bfloat16 g_wq[(size_t)DD * DD];        // Wq bf16
__device__ __nv_bfloat16 g_wk[(size_t)DD * DD];        // Wk bf16
__device__ __nv_bfloat16 g_q [(size_t)MTOT * DD];      // Q bf16
__device__ __nv_bfloat16 g_k [(size_t)MTOT * DD];      // K bf16
__device__ float         g_p [(size_t)BB * SS * SS];   // scores fp32
__device__ __nv_bfloat16 g_pb[(size_t)BB * SS * SS];   // probs bf16
__device__ __nv_bfloat16 g_xt[(size_t)BB * DD * SS];   // x^T bf16 [b][d][s]

// ---------------------------------------------------------------------------
__device__ __forceinline__ u32 smem_u32(const void* p) {
    u32 a;
    asm("{ .reg .u64 t; cvta.to.shared.u64 t, %1; cvt.u32.u64 %0, t; }" : "=r"(a) : "l"(p));
    return a;
}
#define CP_ASYNC16(sa, ga) \
    asm volatile("cp.async.cg.shared.global [%0], [%1], 16;" :: "r"(sa), "l"(ga) : "memory")
#define CP_COMMIT()  asm volatile("cp.async.commit_group;" ::: "memory")
#define CP_WAIT(n)   asm volatile("cp.async.wait_group %0;" :: "n"(n) : "memory")
#define LDSM_X4(r0, r1, r2, r3, addr) \
    asm volatile("ldmatrix.sync.aligned.m8n8.x4.shared.b16 {%0,%1,%2,%3}, [%4];" \
        : "=r"(r0), "=r"(r1), "=r"(r2), "=r"(r3) : "r"(addr))

__device__ __forceinline__ void mma16816(float* c, const u32* a, u32 b0, u32 b1) {
    asm volatile(
        "mma.sync.aligned.m16n8k16.row.col.f32.bf16.bf16.f32 "
        "{%0,%1,%2,%3}, {%4,%5,%6,%7}, {%8,%9}, {%0,%1,%2,%3};"
        : "+f"(c[0]), "+f"(c[1]), "+f"(c[2]), "+f"(c[3])
        : "r"(a[0]), "r"(a[1]), "r"(a[2]), "r"(a[3]), "r"(b0), "r"(b1));
}

// ---------------------------------------------------------------------------
// HMMA GEMM:  C[m,n] = sum_k A[m,k] * B[n,k]  (+bias)(+resid)
// A:[M,K] bf16 K-major, B:[N,K] bf16 K-major. Block 128x128, BK=32.
// 256 threads = 8 warps (4m x 2n), warp tile 32x64, m16n8k16 fragments.
// 3-stage cp.async pipeline, ldmatrix.x4 fragment loads, 1 sync / iter.
// ---------------------------------------------------------------------------
template <bool BIAS, bool RESID, bool OUTBF16>
__global__ __launch_bounds__(256) void mma_gemm(
    const __nv_bfloat16* __restrict__ A, const __nv_bfloat16* __restrict__ B,
    void* __restrict__ Cv,
    const float* __restrict__ bias, const float* __restrict__ resid,
    int N, int K, long aStride, long bStride, long cStride)
{
    extern __shared__ char smem[];
    // layout: A tiles [NSTAGE][128][PITCH], then B tiles [NSTAGE][128][PITCH]
    const u32 smem_base = smem_u32(smem);
    const u32 aTile0 = smem_base;
    const u32 bTile0 = smem_base + NSTAGE * STAGE_BYTES;

    const int tid = threadIdx.x;
    const int wid = tid >> 5, lane = tid & 31;
    const int wm = wid & 3, wn = wid >> 2;          // 4 x 2 warp grid
    const int g = lane >> 2, t = lane & 3;          // mma fragment coords
    const int m0 = blockIdx.y * 128, n0 = blockIdx.x * 128;
    const int z = blockIdx.z;

    A += (size_t)z * aStride + (size_t)m0 * K;
    B += (size_t)z * bStride + (size_t)n0 * K;

    const int NC = K / BK;
    // cp.async mapping: 512 16B segments per operand tile, 2 per thread
    const int r0 = tid >> 2, c0 = (tid & 3) * 8;
    const int r1 = r0 + 64;
    const u32 sA0 = aTile0 + r0 * (PITCH * 2) + c0 * 2;
    const u32 sA1 = aTile0 + r1 * (PITCH * 2) + c0 * 2;
    const u32 sB0 = bTile0 + r0 * (PITCH * 2) + c0 * 2;
    const u32 sB1 = bTile0 + r1 * (PITCH * 2) + c0 * 2;

    // ldmatrix per-lane base addresses (row = lane&15, kcol = (lane>>4)*8)
    const int lr = lane & 15, lk = (lane >> 4) * 8;
    const u32 aLds = aTile0 + (wm * 32 + lr) * (PITCH * 2) + lk * 2;
    const u32 bLds = bTile0 + (wn * 64 + lr) * (PITCH * 2) + lk * 2;

    float acc[2][8][4];
    #pragma unroll
    for (int mt = 0; mt < 2; mt++)
        #pragma unroll
        for (int nt = 0; nt < 8; nt++)
            #pragma unroll
            for (int i = 0; i < 4; i++) acc[mt][nt][i] = 0.f;

    // prologue: stages 0, 1
    #pragma unroll
    for (int s = 0; s < 2; s++) {
        const __nv_bfloat16* Ak = A + (size_t)s * BK;
        const __nv_bfloat16* Bk = B + (size_t)s * BK;
        const u32 so = s * STAGE_BYTES;
        CP_ASYNC16(sA0 + so, Ak + (size_t)r0 * K + c0);
        CP_ASYNC16(sA1 + so, Ak + (size_t)r1 * K + c0);
        CP_ASYNC16(sB0 + so, Bk + (size_t)r0 * K + c0);
        CP_ASYNC16(sB1 + so, Bk + (size_t)r1 * K + c0);
        CP_COMMIT();
    }

    int st = 0;
    for (int c = 0; c < NC; ++c) {
        CP_WAIT(1);                     // stage c's group complete
        __syncthreads();

        // prefetch stage c+2 (empty commit keeps group accounting at tail)
        if (c + 2 < NC) {
            const int ps = (st + 2 >= NSTAGE) ? st + 2 - NSTAGE : st + 2;
            const __nv_bfloat16* Ak = A + (size_t)(c + 2) * BK;
            const __nv_bfloat16* Bk = B + (size_t)(c + 2) * BK;
            const u32 so = ps * STAGE_BYTES;
            CP_ASYNC16(sA0 + so, Ak + (size_t)r0 * K + c0);
            CP_ASYNC16(sA1 + so, Ak + (size_t)r1 * K + c0);
            CP_ASYNC16(sB0 + so, Bk + (size_t)r0 * K + c0);
            CP_ASYNC16(sB1 + so, Bk + (size_t)r1 * K + c0);
        }
        CP_COMMIT();

        const u32 so = st * STAGE_BYTES;
        #pragma unroll
        for (int kk = 0; kk < 2; kk++) {
            u32 a[2][4], b[4][4];
            #pragma unroll
            for (int mt = 0; mt < 2; mt++)
                LDSM_X4(a[mt][0], a[mt][1], a[mt][2], a[mt][3],
                        aLds + so + mt * (16 * PITCH * 2) + kk * 32);
            #pragma unroll
            for (int np = 0; np < 4; np++)
                LDSM_X4(b[np][0], b[np][1], b[np][2], b[np][3],
                        bLds + so + np * (16 * PITCH * 2) + kk * 32);
            // b[np] = { b_{2np}[0], b_{2np+1}[0], b_{2np}[1], b_{2np+1}[1] }
            #pragma unroll
            for (int mt = 0; mt < 2; mt++)
                #pragma unroll
                for (int nt = 0; nt < 8; nt++)
                    mma16816(acc[mt][nt], a[mt], b[nt >> 1][nt & 1], b[nt >> 1][2 + (nt & 1)]);
        }
        st = (st + 1 >= NSTAGE) ? 0 : st + 1;
    }

    // Epilogue
    #pragma unroll
    for (int mt = 0; mt < 2; mt++) {
        #pragma unroll
        for (int nt = 0; nt < 8; nt++) {
            const int row = m0 + wm * 32 + mt * 16 + g;
            const int col = n0 + wn * 64 + nt * 8 + 2 * t;
            float v0 = acc[mt][nt][0], v1 = acc[mt][nt][1];
            float v2 = acc[mt][nt][2], v3 = acc[mt][nt][3];
            if (BIAS) {
                float b0 = bias[col], b1 = bias[col + 1];
                v0 += b0; v1 += b1; v2 += b0; v3 += b1;
            }
            if (OUTBF16) {
                __nv_bfloat16* Cb = (__nv_bfloat16*)Cv + (size_t)z * cStride;
                *(__nv_bfloat162*)(Cb + (size_t)row * N + col) = __floats2bfloat162_rn(v0, v1);
                *(__nv_bfloat162*)(Cb + (size_t)(row + 8) * N + col) = __floats2bfloat162_rn(v2, v3);
            } else {
                float* Cf = (float*)Cv + (size_t)z * cStride;
                if (RESID) {
                    const float* R = resid + (size_t)z * cStride;
                    float2 ra = *(const float2*)(R + (size_t)row * N + col);
                    float2 rb = *(const float2*)(R + (size_t)(row + 8) * N + col);
                    v0 += ra.x; v1 += ra.y; v2 += rb.x; v3 += rb.y;
                }
                *(float2*)(Cf + (size_t)row * N + col) = make_float2(v0, v1);
                *(float2*)(Cf + (size_t)(row + 8) * N + col) = make_float2(v2, v3);
            }
        }
    }
}

// ---------------------------------------------------------------------------
// Reductions + elementwise kernels
// ---------------------------------------------------------------------------
__device__ __forceinline__ float blockReduceSum(float v) {
    __shared__ float sh[32];
    int lane = threadIdx.x & 31, wid = threadIdx.x >> 5;
    #pragma unroll
    for (int o = 16; o; o >>= 1) v += __shfl_down_sync(0xffffffffu, v, o);
    if (lane == 0) sh[wid] = v;
    __syncthreads();
    float r = (threadIdx.x < (blockDim.x >> 5)) ? sh[threadIdx.x] : 0.f;
    if (wid == 0) {
        #pragma unroll
        for (int o = 16; o; o >>= 1) r += __shfl_down_sync(0xffffffffu, r, o);
        if (lane == 0) sh[0] = r;
    }
    __syncthreads();
    float out = sh[0];
    __syncthreads();
    return out;
}
__device__ __forceinline__ float blockReduceMax(float v) {
    __shared__ float sh[32];
    int lane = threadIdx.x & 31, wid = threadIdx.x >> 5;
    #pragma unroll
    for (int o = 16; o; o >>= 1) v = fmaxf(v, __shfl_down_sync(0xffffffffu, v, o));
    if (lane == 0) sh[wid] = v;
    __syncthreads();
    float r = (threadIdx.x < (blockDim.x >> 5)) ? sh[threadIdx.x] : -3.4e38f;
    if (wid == 0) {
        #pragma unroll
        for (int o = 16; o; o >>= 1) r = fmaxf(r, __shfl_down_sync(0xffffffffu, r, o));
        if (lane == 0) sh[0] = r;
    }
    __syncthreads();
    float out = sh[0];
    __syncthreads();
    return out;
}

__global__ __launch_bounds__(256) void ln_kernel(const float* __restrict__ x,
                                                 const float* __restrict__ g,
                                                 const float* __restrict__ b) {
    int row = blockIdx.x, t = threadIdx.x;
    const float* xr = x + (size_t)row * DD;
    float v[3];
    #pragma unroll
    for (int i = 0; i < 3; i++) v[i] = xr[t + i * 256];
    float mean = blockReduceSum(v[0] + v[1] + v[2]) * (1.0f / DD);
    float q = 0.f;
    #pragma unroll
    for (int i = 0; i < 3; i++) { float d = v[i] - mean; q += d * d; }
    float inv = rsqrtf(blockReduceSum(q) * (1.0f / DD) + 1e-5f);
    __nv_bfloat16* o = g_xn + (size_t)row * DD;
    #pragma unroll
    for (int i = 0; i < 3; i++) {
        int c = t + i * 256;
        o[c] = __float2bfloat16_rn((v[i] - mean) * inv * g[c] + b[c]);
    }
}

__global__ __launch_bounds__(256) void convw_kernel(const float* __restrict__ Wq,
                                                    const float* __restrict__ Wk) {
    int i = blockIdx.x * 256 + threadIdx.x;
    if (i < DD * DD) {
        g_wq[i] = __float2bfloat16_rn(Wq[i]);
        g_wk[i] = __float2bfloat16_rn(Wk[i]);
    }
}

__global__ __launch_bounds__(256) void transpose_kernel(const float* __restrict__ x) {
    __shared__ float t[32][33];
    int b = blockIdx.z;
    int s0 = blockIdx.x * 32, d0 = blockIdx.y * 32;
    int tx = threadIdx.x & 31, ty = threadIdx.x >> 5;
    #pragma unroll
    for (int i = 0; i < 4; i++)
        t[ty + i * 8][tx] = x[(size_t)b * SS * DD + (size_t)(s0 + ty + i * 8) * DD + d0 + tx];
    __syncthreads();
    #pragma unroll
    for (int i = 0; i < 4; i++)
        g_xt[(size_t)b * DD * SS + (size_t)(d0 + ty + i * 8) * SS + s0 + tx] =
            __float2bfloat16_rn(t[tx][ty + i * 8]);
}

__global__ __launch_bounds__(256) void softmax_kernel() {
    const float alpha = 0.036084391824351615f;   // 1/sqrt(768)
    const float4* row = (const float4*)(g_p + (size_t)blockIdx.x * SS);
    __nv_bfloat16* orow = g_pb + (size_t)blockIdx.x * SS;
    int t = threadIdx.x;
    float4 va = row[t];
    float4 vb = row[t + 256];
    float v[8] = {va.x, va.y, va.z, va.w, vb.x, vb.y, vb.z, vb.w};
    #pragma unroll
    for (int i = 0; i < 8; i++) v[i] *= alpha;
    float m = v[0];
    #pragma unroll
    for (int i = 1; i < 8; i++) m = fmaxf(m, v[i]);
    m = blockReduceMax(m);
    float s = 0.f;
    #pragma unroll
    for (int i = 0; i < 8; i++) { v[i] = __expf(v[i] - m); s += v[i]; }
    s = blockReduceSum(s);
    float inv = 1.0f / s;
    __nv_bfloat162 o01 = __floats2bfloat162_rn(v[0] * inv, v[1] * inv);
    __nv_bfloat162 o23 = __floats2bfloat162_rn(v[2] * inv, v[3] * inv);
    __nv_bfloat162 o45 = __floats2bfloat162_rn(v[4] * inv, v[5] * inv);
    __nv_bfloat162 o67 = __floats2bfloat162_rn(v[6] * inv, v[7] * inv);
    uint2 pa, pb;
    pa.x = *(u32*)&o01; pa.y = *(u32*)&o23;
    pb.x = *(u32*)&o45; pb.y = *(u32*)&o67;
    *(uint2*)(orow + t * 4) = pa;
    *(uint2*)(orow + (t + 256) * 4) = pb;
}

// ---------------------------------------------------------------------------
extern "C" void kernel_launch(void* const* d_in, const int* in_sizes, int n_in,
                              void* d_out, int out_size) {
    const float* x    = (const float*)d_in[0];
    const float* ln_g = (const float*)d_in[1];
    const float* ln_b = (const float*)d_in[2];
    const float* Wq   = (const float*)d_in[3];
    const float* bq   = (const float*)d_in[4];
    const float* Wk   = (const float*)d_in[5];
    const float* bk   = (const float*)d_in[6];
    float* out = (float*)d_out;

    const int SMEM_DYN = NSTAGE * STAGE_BYTES * 2;   // 61440
    cudaFuncSetAttribute(mma_gemm<true,  false, true >, cudaFuncAttributeMaxDynamicSharedMemorySize, SMEM_DYN);
    cudaFuncSetAttribute(mma_gemm<false, false, false>, cudaFuncAttributeMaxDynamicSharedMemorySize, SMEM_DYN);
    cudaFuncSetAttribute(mma_gemm<false, true,  false>, cudaFuncAttributeMaxDynamicSharedMemorySize, SMEM_DYN);

    __nv_bfloat16 *p_xn, *p_wq, *p_wk, *p_q, *p_k, *p_pb, *p_xt;
    float* p_p;
    cudaGetSymbolAddress((void**)&p_xn, g_xn);
    cudaGetSymbolAddress((void**)&p_wq, g_wq);
    cudaGetSymbolAddress((void**)&p_wk, g_wk);
    cudaGetSymbolAddress((void**)&p_q,  g_q);
    cudaGetSymbolAddress((void**)&p_k,  g_k);
    cudaGetSymbolAddress((void**)&p_p,  g_p);
    cudaGetSymbolAddress((void**)&p_pb, g_pb);
    cudaGetSymbolAddress((void**)&p_xt, g_xt);

    ln_kernel<<<MTOT, 256>>>(x, ln_g, ln_b);
    convw_kernel<<<(DD * DD + 255) / 256, 256>>>(Wq, Wk);
    transpose_kernel<<<dim3(SS / 32, DD / 32, BB), 256>>>(x);

    // Q = xn @ Wq^T + bq ; K = xn @ Wk^T + bk   (M=16384, N=768, K=768)
    mma_gemm<true, false, true><<<dim3(DD / 128, MTOT / 128, 1), 256, SMEM_DYN>>>(
        p_xn, p_wq, p_q, bq, nullptr, DD, DD, 0, 0, 0);
    mma_gemm<true, false, true><<<dim3(DD / 128, MTOT / 128, 1), 256, SMEM_DYN>>>(
        p_xn, p_wk, p_k, bk, nullptr, DD, DD, 0, 0, 0);

    // scores = Q @ K^T (unscaled; softmax applies 1/sqrt(D))
    mma_gemm<false, false, false><<<dim3(SS / 128, SS / 128, BB), 256, SMEM_DYN>>>(
        p_q, p_k, p_p, nullptr, nullptr, SS, DD,
        (long)SS * DD, (long)SS * DD, (long)SS * SS);

    softmax_kernel<<<BB * SS, 256>>>();

    // out = P @ x + x   (A = P bf16 [S,S], B = x^T bf16 [D,S])
    mma_gemm<false, true, false><<<dim3(DD / 128, SS / 128, BB), 256, SMEM_DYN>>>(
        p_pb, p_xt, out, nullptr, x, DD, SS,
        (long)SS * SS, (long)DD * SS, (long)SS * DD);
}